// round 1
// baseline (speedup 1.0000x reference)
#include <cuda_runtime.h>
#include <cstdint>

#define BATCH   2048
#define TT      50
#define NNODES  23
#define FF      4
#define HH      64
#define FUT     10
#define BPC     4                 // batches per CTA
#define ROWS    (BPC*NNODES)      // 92
#define THREADS 512
#define RS      68                // padded row stride (floats) for 64-wide rows

// ---- smem layout (floats) ----
// sWI   12288   [g3*64+j][k]  == global row-major of W_ih
// sWH   12288
// sSup  92*68
// sSpa  92*68
// sH    92*68
// sAdj  4*23*24
// sX    4*23*4
// sWg   64*4
// sbg   64
// sbi   192
// sbh   192
// sWd1  32*64
// sbd1  32
// sWd2  4*32
// sbd2  4
#define SMEM_FLOATS (12288+12288+3*ROWS*RS+BPC*NNODES*24+BPC*NNODES*FF+256+64+192+192+2048+32+128+4)

__device__ __forceinline__ float sigmoidf_(float x) {
    return __fdividef(1.f, 1.f + __expf(-x));
}
__device__ __forceinline__ float tanhf_(float x) {
    return __fdividef(2.f, 1.f + __expf(-2.f * x)) - 1.f;
}

extern "C" __global__ void __launch_bounds__(THREADS, 1)
gwm_kernel(const float* __restrict__ x_seq, const float* __restrict__ adj_seq,
           const float* __restrict__ W_gcn, const float* __restrict__ b_gcn,
           const float* __restrict__ W_ih,  const float* __restrict__ W_hh,
           const float* __restrict__ b_ih,  const float* __restrict__ b_hh,
           const float* __restrict__ W_d1,  const float* __restrict__ b_d1,
           const float* __restrict__ W_d2,  const float* __restrict__ b_d2,
           float* __restrict__ out)
{
    extern __shared__ float sm[];
    float* sWI  = sm;
    float* sWH  = sWI + 12288;
    float* sSup = sWH + 12288;
    float* sSpa = sSup + ROWS*RS;
    float* sH   = sSpa + ROWS*RS;
    float* sAdj = sH   + ROWS*RS;           // [r][24]
    float* sX   = sAdj + BPC*NNODES*24;     // [r][4]
    float* sWg  = sX   + BPC*NNODES*FF;     // [j][4]
    float* sbg  = sWg  + 256;
    float* sbi  = sbg  + 64;
    float* sbh  = sbi  + 192;
    float* sWd1 = sbh  + 192;               // [q][64]
    float* sbd1 = sWd1 + 2048;
    float* sWd2 = sbd1 + 32;                // [f][32]
    float* sbd2 = sWd2 + 128;

    const int tid  = threadIdx.x;
    const int w    = tid >> 5;
    const int lane = tid & 31;
    const int b0   = blockIdx.x * BPC;

    // ---- load all weights once ----
    for (int e = tid; e < 12288; e += THREADS) sWI[e] = W_ih[e];
    for (int e = tid; e < 12288; e += THREADS) sWH[e] = W_hh[e];
    for (int e = tid; e < 256;   e += THREADS) sWg[e] = W_gcn[e];
    for (int e = tid; e < 2048;  e += THREADS) sWd1[e] = W_d1[e];
    if (tid < 64)  sbg[tid] = b_gcn[tid];
    if (tid < 192) sbi[tid] = b_ih[tid];
    if (tid >= 192 && tid < 384) sbh[tid-192] = b_hh[tid-192];
    if (tid < 32)  sbd1[tid] = b_d1[tid];
    if (tid < 128) sWd2[tid] = W_d2[tid];
    if (tid < 4)   sbd2[tid] = b_d2[tid];
    // h0 = 0
    for (int e = tid; e < ROWS*RS; e += THREADS) sH[e] = 0.f;
    __syncthreads();

    for (int t = 0; t < TT + FUT; ++t) {
        const bool hist = (t < TT);
        if (hist) {
            // load adj_t and x_t for 4 batches
            for (int e = tid; e < BPC*NNODES*NNODES; e += THREADS) {
                int bl = e / (NNODES*NNODES);
                int i  = e - bl*(NNODES*NNODES);
                int n  = i / NNODES, m = i - n*NNODES;
                sAdj[(bl*NNODES + n)*24 + m] =
                    adj_seq[((size_t)(b0+bl)*TT + t)*(NNODES*NNODES) + i];
            }
            for (int e = tid; e < BPC*NNODES*FF; e += THREADS) {
                int bl = e / (NNODES*FF);
                int i  = e - bl*(NNODES*FF);
                sX[e] = x_seq[((size_t)(b0+bl)*TT + t)*(NNODES*FF) + i];
            }
            __syncthreads();
        }

        // ---- phase 1: support = x @ Wg^T + bg ----
        for (int e = tid; e < ROWS*HH; e += THREADS) {
            int r = e >> 6, j = e & 63;
            const float* xp = sX + r*FF;
            float v = sbg[j];
            v = fmaf(xp[0], sWg[j*4+0], v);
            v = fmaf(xp[1], sWg[j*4+1], v);
            v = fmaf(xp[2], sWg[j*4+2], v);
            v = fmaf(xp[3], sWg[j*4+3], v);
            sSup[r*RS + j] = v;
        }
        __syncthreads();

        // ---- phase 2: spatial = relu(adj @ support) ----
        {
            const int rh = lane >> 4, jq = lane & 15;
            for (int p = w; p < 46; p += 16) {
                int r = 2*p + rh;                    // 0..91
                int bl = r / NNODES;
                const float* arow = sAdj + r*24;
                const float* supb = sSup + (bl*NNODES)*RS;
                float4 acc = make_float4(0.f,0.f,0.f,0.f);
#pragma unroll
                for (int m = 0; m < NNODES; ++m) {
                    float a = arow[m];
                    float4 s = *(const float4*)(supb + m*RS + 4*jq);
                    acc.x = fmaf(a, s.x, acc.x);
                    acc.y = fmaf(a, s.y, acc.y);
                    acc.z = fmaf(a, s.z, acc.z);
                    acc.w = fmaf(a, s.w, acc.w);
                }
                acc.x = fmaxf(acc.x, 0.f); acc.y = fmaxf(acc.y, 0.f);
                acc.z = fmaxf(acc.z, 0.f); acc.w = fmaxf(acc.w, 0.f);
                *(float4*)(sSpa + r*RS + 4*jq) = acc;
            }
        }
        __syncthreads();

        // ---- phase 3: GRU gates + h update ----
        float hnew[3][4];
        {
            const int j0 = w * 4;
#pragma unroll
            for (int rg = 0; rg < 3; ++rg) {
                int r  = rg*32 + lane;
                int rr = (r < ROWS) ? r : 0;
                const float4* sp = (const float4*)(sSpa + rr*RS);
                const float4* hp = (const float4*)(sH   + rr*RS);
                float aI[4][3], aH[4][3];
#pragma unroll
                for (int jj = 0; jj < 4; ++jj)
#pragma unroll
                    for (int g3 = 0; g3 < 3; ++g3) { aI[jj][g3] = 0.f; aH[jj][g3] = 0.f; }
#pragma unroll 4
                for (int kq = 0; kq < 16; ++kq) {
                    float4 s  = sp[kq];
                    float4 hh = hp[kq];
#pragma unroll
                    for (int jj = 0; jj < 4; ++jj) {
#pragma unroll
                        for (int g3 = 0; g3 < 3; ++g3) {
                            const float4 wi = *(const float4*)(sWI + (g3*64 + j0 + jj)*64 + kq*4);
                            const float4 wh = *(const float4*)(sWH + (g3*64 + j0 + jj)*64 + kq*4);
                            float a = aI[jj][g3];
                            a = fmaf(s.x, wi.x, a); a = fmaf(s.y, wi.y, a);
                            a = fmaf(s.z, wi.z, a); a = fmaf(s.w, wi.w, a);
                            aI[jj][g3] = a;
                            float b = aH[jj][g3];
                            b = fmaf(hh.x, wh.x, b); b = fmaf(hh.y, wh.y, b);
                            b = fmaf(hh.z, wh.z, b); b = fmaf(hh.w, wh.w, b);
                            aH[jj][g3] = b;
                        }
                    }
                }
#pragma unroll
                for (int jj = 0; jj < 4; ++jj) {
                    int j = j0 + jj;
                    float gr = aI[jj][0] + sbi[j]      + aH[jj][0] + sbh[j];
                    float gz = aI[jj][1] + sbi[64+j]   + aH[jj][1] + sbh[64+j];
                    float rr_ = sigmoidf_(gr);
                    float zz  = sigmoidf_(gz);
                    float nn  = tanhf_(aI[jj][2] + sbi[128+j] + rr_*(aH[jj][2] + sbh[128+j]));
                    float hold = sH[rr*RS + j];
                    hnew[rg][jj] = (1.f - zz)*nn + zz*hold;
                }
            }
        }
        __syncthreads();   // all reads of sH / sSpa complete
        {
            const int j0 = w * 4;
#pragma unroll
            for (int rg = 0; rg < 3; ++rg) {
                int r = rg*32 + lane;
                if (r < ROWS) {
#pragma unroll
                    for (int jj = 0; jj < 4; ++jj) sH[r*RS + j0 + jj] = hnew[rg][jj];
                }
            }
        }
        __syncthreads();

        // ---- decode (future steps only) ----
        if (!hist) {
            const int s = t - TT;
            // d1 = relu(h @ Wd1^T + bd1) -> stored into sSup (free now)
            if (w < 8) {
                const int q0 = w * 4;
#pragma unroll
                for (int rg = 0; rg < 3; ++rg) {
                    int r  = rg*32 + lane;
                    int rr = (r < ROWS) ? r : 0;
                    const float4* hp = (const float4*)(sH + rr*RS);
                    float acc[4] = {0.f,0.f,0.f,0.f};
#pragma unroll 4
                    for (int kq = 0; kq < 16; ++kq) {
                        float4 hh = hp[kq];
#pragma unroll
                        for (int jj = 0; jj < 4; ++jj) {
                            const float4 wd = *(const float4*)(sWd1 + (q0+jj)*64 + kq*4);
                            float a = acc[jj];
                            a = fmaf(hh.x, wd.x, a); a = fmaf(hh.y, wd.y, a);
                            a = fmaf(hh.z, wd.z, a); a = fmaf(hh.w, wd.w, a);
                            acc[jj] = a;
                        }
                    }
                    if (r < ROWS) {
#pragma unroll
                        for (int jj = 0; jj < 4; ++jj)
                            sSup[r*RS + q0 + jj] = fmaxf(acc[jj] + sbd1[q0+jj], 0.f);
                    }
                }
            }
            __syncthreads();
            // nx = d1 @ Wd2^T + bd2 -> new x and global output
            for (int e = tid; e < ROWS*FF; e += THREADS) {
                int r = e >> 2, f = e & 3;
                float v = sbd2[f];
#pragma unroll
                for (int q = 0; q < 32; ++q)
                    v = fmaf(sSup[r*RS + q], sWd2[f*32 + q], v);
                sX[e] = v;
                int bl = r / NNODES, n = r - bl*NNODES;
                out[(((size_t)(b0+bl)*FUT + s)*NNODES + n)*FF + f] = v;
            }
            __syncthreads();
        }
    }
}

extern "C" void kernel_launch(void* const* d_in, const int* in_sizes, int n_in,
                              void* d_out, int out_size) {
    const float* x_seq  = (const float*)d_in[0];
    const float* adj    = (const float*)d_in[1];
    const float* W_gcn  = (const float*)d_in[2];
    const float* b_gcn  = (const float*)d_in[3];
    const float* W_ih   = (const float*)d_in[4];
    const float* W_hh   = (const float*)d_in[5];
    const float* b_ih   = (const float*)d_in[6];
    const float* b_hh   = (const float*)d_in[7];
    const float* W_d1   = (const float*)d_in[8];
    const float* b_d1   = (const float*)d_in[9];
    const float* W_d2   = (const float*)d_in[10];
    const float* b_d2   = (const float*)d_in[11];
    float* out = (float*)d_out;

    const int smem_bytes = SMEM_FLOATS * (int)sizeof(float);
    cudaFuncSetAttribute(gwm_kernel, cudaFuncAttributeMaxDynamicSharedMemorySize, smem_bytes);
    gwm_kernel<<<BATCH / BPC, THREADS, smem_bytes>>>(
        x_seq, adj, W_gcn, b_gcn, W_ih, W_hh, b_ih, b_hh,
        W_d1, b_d1, W_d2, b_d2, out);
}

// round 2
// speedup vs baseline: 1.3173x; 1.3173x over previous
#include <cuda_runtime.h>
#include <cstdint>

#define BATCH   2048
#define TT      50
#define NNODES  23
#define FF      4
#define HH      64
#define FUT     10
#define BPC     4                 // batches per CTA
#define ROWS    (BPC*NNODES)      // 92
#define THREADS 512
#define RS      68                // padded row stride (floats); 68*4=272B = 17*16B (16B aligned, conflict-free for .128)

#define SMEM_FLOATS (12288+12288+3*ROWS*RS+BPC*NNODES*24+BPC*NNODES*FF+256+64+192+192+2048+32+128+4)

typedef unsigned long long u64;

// packed fp32x2 FMA: d.lo += a.lo*b.lo ; d.hi += a.hi*b.hi  (full-rate fma pipe on sm_103a)
__device__ __forceinline__ void fma2(u64& d, u64 a, u64 b) {
    asm("fma.rn.f32x2 %0, %1, %2, %0;" : "+l"(d) : "l"(a), "l"(b));
}
__device__ __forceinline__ float2 unpk(u64 v) {
    float2 r; asm("mov.b64 {%0, %1}, %2;" : "=f"(r.x), "=f"(r.y) : "l"(v)); return r;
}
__device__ __forceinline__ u64 dup2(float a) {
    u64 r; asm("mov.b64 %0, {%1, %1};" : "=l"(r) : "f"(a)); return r;
}

__device__ __forceinline__ float sigmoidf_(float x) {
    return __fdividef(1.f, 1.f + __expf(-x));
}
__device__ __forceinline__ float tanhf_(float x) {
    return __fdividef(2.f, 1.f + __expf(-2.f * x)) - 1.f;
}

extern "C" __global__ void __launch_bounds__(THREADS, 1)
gwm_kernel(const float* __restrict__ x_seq, const float* __restrict__ adj_seq,
           const float* __restrict__ W_gcn, const float* __restrict__ b_gcn,
           const float* __restrict__ W_ih,  const float* __restrict__ W_hh,
           const float* __restrict__ b_ih,  const float* __restrict__ b_hh,
           const float* __restrict__ W_d1,  const float* __restrict__ b_d1,
           const float* __restrict__ W_d2,  const float* __restrict__ b_d2,
           float* __restrict__ out)
{
    extern __shared__ float sm[];
    float* sWI  = sm;                       // [g3*64+j][64]
    float* sWH  = sWI + 12288;
    float* sSup = sWH + 12288;              // support; reused as z-scratch in phase 3; d1 in decode
    float* sSpa = sSup + ROWS*RS;
    float* sH   = sSpa + ROWS*RS;
    float* sAdj = sH   + ROWS*RS;           // [r][24]
    float* sX   = sAdj + BPC*NNODES*24;     // [r][4]
    float* sWg  = sX   + BPC*NNODES*FF;     // [j][4]
    float* sbg  = sWg  + 256;
    float* sbi  = sbg  + 64;
    float* sbh  = sbi  + 192;
    float* sWd1 = sbh  + 192;               // [q][64]
    float* sbd1 = sWd1 + 2048;
    float* sWd2 = sbd1 + 32;                // [f][32]
    float* sbd2 = sWd2 + 128;

    const int tid  = threadIdx.x;
    const int w    = tid >> 5;
    const int lane = tid & 31;
    const int b0   = blockIdx.x * BPC;

    // ---- load all weights once ----
    for (int e = tid; e < 12288; e += THREADS) sWI[e] = W_ih[e];
    for (int e = tid; e < 12288; e += THREADS) sWH[e] = W_hh[e];
    for (int e = tid; e < 256;   e += THREADS) sWg[e] = W_gcn[e];
    for (int e = tid; e < 2048;  e += THREADS) sWd1[e] = W_d1[e];
    if (tid < 64)  sbg[tid] = b_gcn[tid];
    if (tid < 192) sbi[tid] = b_ih[tid];
    if (tid >= 192 && tid < 384) sbh[tid-192] = b_hh[tid-192];
    if (tid < 32)  sbd1[tid] = b_d1[tid];
    if (tid < 128) sWd2[tid] = W_d2[tid];
    if (tid < 4)   sbd2[tid] = b_d2[tid];
    for (int e = tid; e < ROWS*RS; e += THREADS) sH[e] = 0.f;
    __syncthreads();

    // phase-3 row mapping: lane -> rows lane, lane+32, lane+64
    const int j0 = w * 4;
    int  rr_[3]; bool val_[3];
#pragma unroll
    for (int rg = 0; rg < 3; ++rg) {
        int r = rg*32 + lane;
        val_[rg] = (r < ROWS);
        rr_[rg]  = val_[rg] ? r : 0;
    }

    for (int t = 0; t < TT + FUT; ++t) {
        const bool hist = (t < TT);
        if (hist) {
            for (int e = tid; e < BPC*NNODES*NNODES; e += THREADS) {
                int bl = e / (NNODES*NNODES);
                int i  = e - bl*(NNODES*NNODES);
                int n  = i / NNODES, m = i - n*NNODES;
                sAdj[(bl*NNODES + n)*24 + m] =
                    adj_seq[((size_t)(b0+bl)*TT + t)*(NNODES*NNODES) + i];
            }
            for (int e = tid; e < BPC*NNODES*FF; e += THREADS) {
                int bl = e / (NNODES*FF);
                int i  = e - bl*(NNODES*FF);
                sX[e] = x_seq[((size_t)(b0+bl)*TT + t)*(NNODES*FF) + i];
            }
            __syncthreads();
        }

        // ---- phase 1: support = x @ Wg^T + bg ----
        for (int e = tid; e < ROWS*HH; e += THREADS) {
            int r = e >> 6, j = e & 63;
            const float* xp = sX + r*FF;
            float v = sbg[j];
            v = fmaf(xp[0], sWg[j*4+0], v);
            v = fmaf(xp[1], sWg[j*4+1], v);
            v = fmaf(xp[2], sWg[j*4+2], v);
            v = fmaf(xp[3], sWg[j*4+3], v);
            sSup[r*RS + j] = v;
        }
        __syncthreads();

        // ---- phase 2: spatial = relu(adj @ support), packed ----
        {
            const int rh = lane >> 4, jq = lane & 15;
            for (int p = w; p < 46; p += 16) {
                int r = 2*p + rh;
                int bl = r / NNODES;
                const float* arow = sAdj + r*24;
                const float* supb = sSup + (bl*NNODES)*RS;
                u64 a0 = 0ull, a1 = 0ull;
#pragma unroll
                for (int m = 0; m < NNODES; ++m) {
                    u64 am = dup2(arow[m]);
                    ulonglong2 s = *(const ulonglong2*)(supb + m*RS + 4*jq);
                    fma2(a0, am, s.x);
                    fma2(a1, am, s.y);
                }
                float2 f0 = unpk(a0), f1 = unpk(a1);
                float4 o;
                o.x = fmaxf(f0.x, 0.f); o.y = fmaxf(f0.y, 0.f);
                o.z = fmaxf(f1.x, 0.f); o.w = fmaxf(f1.y, 0.f);
                *(float4*)(sSpa + r*RS + 4*jq) = o;
            }
        }
        __syncthreads();

        // ---- phase 3 pass A: gates r,z (merged input+hidden accumulators) ----
        float rv[3][4];
        {
            u64 aR[3][4], aZ[3][4];
#pragma unroll
            for (int rg = 0; rg < 3; ++rg)
#pragma unroll
                for (int jj = 0; jj < 4; ++jj) { aR[rg][jj] = 0ull; aZ[rg][jj] = 0ull; }

            for (int kq = 0; kq < 16; ++kq) {
                ulonglong2 sv[3], hv[3];
#pragma unroll
                for (int rg = 0; rg < 3; ++rg) {
                    sv[rg] = *(const ulonglong2*)(sSpa + rr_[rg]*RS + kq*4);
                    hv[rg] = *(const ulonglong2*)(sH   + rr_[rg]*RS + kq*4);
                }
#pragma unroll
                for (int jj = 0; jj < 4; ++jj) {
                    const int jr = j0 + jj;
                    ulonglong2 wiR = *(const ulonglong2*)(sWI + jr*64        + kq*4);
                    ulonglong2 whR = *(const ulonglong2*)(sWH + jr*64        + kq*4);
                    ulonglong2 wiZ = *(const ulonglong2*)(sWI + (64+jr)*64   + kq*4);
                    ulonglong2 whZ = *(const ulonglong2*)(sWH + (64+jr)*64   + kq*4);
#pragma unroll
                    for (int rg = 0; rg < 3; ++rg) {
                        fma2(aR[rg][jj], sv[rg].x, wiR.x); fma2(aR[rg][jj], sv[rg].y, wiR.y);
                        fma2(aR[rg][jj], hv[rg].x, whR.x); fma2(aR[rg][jj], hv[rg].y, whR.y);
                        fma2(aZ[rg][jj], sv[rg].x, wiZ.x); fma2(aZ[rg][jj], sv[rg].y, wiZ.y);
                        fma2(aZ[rg][jj], hv[rg].x, whZ.x); fma2(aZ[rg][jj], hv[rg].y, whZ.y);
                    }
                }
            }
#pragma unroll
            for (int rg = 0; rg < 3; ++rg)
#pragma unroll
                for (int jj = 0; jj < 4; ++jj) {
                    const int j = j0 + jj;
                    float2 pr = unpk(aR[rg][jj]);
                    float2 pz = unpk(aZ[rg][jj]);
                    rv[rg][jj] = sigmoidf_(pr.x + pr.y + sbi[j] + sbh[j]);
                    float z    = sigmoidf_(pz.x + pz.y + sbi[64+j] + sbh[64+j]);
                    if (val_[rg]) sSup[rr_[rg]*RS + j] = z;   // park z (own thread reads it back)
                }
        }

        // ---- phase 3 pass B: gate n + h update ----
        float hnew[3][4];
        {
            u64 aNI[3][4], aNH[3][4];
#pragma unroll
            for (int rg = 0; rg < 3; ++rg)
#pragma unroll
                for (int jj = 0; jj < 4; ++jj) { aNI[rg][jj] = 0ull; aNH[rg][jj] = 0ull; }

            for (int kq = 0; kq < 16; ++kq) {
                ulonglong2 sv[3], hv[3];
#pragma unroll
                for (int rg = 0; rg < 3; ++rg) {
                    sv[rg] = *(const ulonglong2*)(sSpa + rr_[rg]*RS + kq*4);
                    hv[rg] = *(const ulonglong2*)(sH   + rr_[rg]*RS + kq*4);
                }
#pragma unroll
                for (int jj = 0; jj < 4; ++jj) {
                    const int jr = j0 + jj;
                    ulonglong2 wiN = *(const ulonglong2*)(sWI + (128+jr)*64 + kq*4);
                    ulonglong2 whN = *(const ulonglong2*)(sWH + (128+jr)*64 + kq*4);
#pragma unroll
                    for (int rg = 0; rg < 3; ++rg) {
                        fma2(aNI[rg][jj], sv[rg].x, wiN.x); fma2(aNI[rg][jj], sv[rg].y, wiN.y);
                        fma2(aNH[rg][jj], hv[rg].x, whN.x); fma2(aNH[rg][jj], hv[rg].y, whN.y);
                    }
                }
            }
#pragma unroll
            for (int rg = 0; rg < 3; ++rg)
#pragma unroll
                for (int jj = 0; jj < 4; ++jj) {
                    const int j = j0 + jj;
                    float2 pi = unpk(aNI[rg][jj]);
                    float2 ph = unpk(aNH[rg][jj]);
                    float nn = tanhf_(pi.x + pi.y + sbi[128+j] +
                                      rv[rg][jj] * (ph.x + ph.y + sbh[128+j]));
                    float z    = val_[rg] ? sSup[rr_[rg]*RS + j] : 0.f;
                    float hold = sH[rr_[rg]*RS + j];
                    hnew[rg][jj] = (1.f - z)*nn + z*hold;
                }
        }
        __syncthreads();   // all reads of sH / sSpa complete
#pragma unroll
        for (int rg = 0; rg < 3; ++rg)
            if (val_[rg]) {
#pragma unroll
                for (int jj = 0; jj < 4; ++jj) sH[rr_[rg]*RS + j0 + jj] = hnew[rg][jj];
            }
        __syncthreads();

        // ---- decode (future steps only) ----
        if (!hist) {
            const int s = t - TT;
            if (w < 8) {
                const int q0 = w * 4;
#pragma unroll
                for (int rg = 0; rg < 3; ++rg) {
                    int r  = rg*32 + lane;
                    int rr = (r < ROWS) ? r : 0;
                    const float4* hp = (const float4*)(sH + rr*RS);
                    float acc[4] = {0.f,0.f,0.f,0.f};
#pragma unroll 4
                    for (int kq = 0; kq < 16; ++kq) {
                        float4 hh = hp[kq];
#pragma unroll
                        for (int jj = 0; jj < 4; ++jj) {
                            const float4 wd = *(const float4*)(sWd1 + (q0+jj)*64 + kq*4);
                            float a = acc[jj];
                            a = fmaf(hh.x, wd.x, a); a = fmaf(hh.y, wd.y, a);
                            a = fmaf(hh.z, wd.z, a); a = fmaf(hh.w, wd.w, a);
                            acc[jj] = a;
                        }
                    }
                    if (r < ROWS) {
#pragma unroll
                        for (int jj = 0; jj < 4; ++jj)
                            sSup[r*RS + q0 + jj] = fmaxf(acc[jj] + sbd1[q0+jj], 0.f);
                    }
                }
            }
            __syncthreads();
            for (int e = tid; e < ROWS*FF; e += THREADS) {
                int r = e >> 2, f = e & 3;
                float v = sbd2[f];
#pragma unroll
                for (int q = 0; q < 32; ++q)
                    v = fmaf(sSup[r*RS + q], sWd2[f*32 + q], v);
                sX[e] = v;
                int bl = r / NNODES, n = r - bl*NNODES;
                out[(((size_t)(b0+bl)*FUT + s)*NNODES + n)*FF + f] = v;
            }
            __syncthreads();
        }
    }
}

extern "C" void kernel_launch(void* const* d_in, const int* in_sizes, int n_in,
                              void* d_out, int out_size) {
    const float* x_seq  = (const float*)d_in[0];
    const float* adj    = (const float*)d_in[1];
    const float* W_gcn  = (const float*)d_in[2];
    const float* b_gcn  = (const float*)d_in[3];
    const float* W_ih   = (const float*)d_in[4];
    const float* W_hh   = (const float*)d_in[5];
    const float* b_ih   = (const float*)d_in[6];
    const float* b_hh   = (const float*)d_in[7];
    const float* W_d1   = (const float*)d_in[8];
    const float* b_d1   = (const float*)d_in[9];
    const float* W_d2   = (const float*)d_in[10];
    const float* b_d2   = (const float*)d_in[11];
    float* out = (float*)d_out;

    const int smem_bytes = SMEM_FLOATS * (int)sizeof(float);
    cudaFuncSetAttribute(gwm_kernel, cudaFuncAttributeMaxDynamicSharedMemorySize, smem_bytes);
    gwm_kernel<<<BATCH / BPC, THREADS, smem_bytes>>>(
        x_seq, adj, W_gcn, b_gcn, W_ih, W_hh, b_ih, b_hh,
        W_d1, b_d1, W_d2, b_d2, out);
}